// round 16
// baseline (speedup 1.0000x reference)
#include <cuda_runtime.h>
#include <cuda_bf16.h>

#define MOD 26
#define NN 64
#define BB 1024
#define NROWS 4096

__device__ constexpr float H_COS[26] = {
    1.0f,         0.97094182f,  0.88545603f,  0.74851075f,  0.56806475f,
    0.35460489f,  0.12053668f, -0.12053668f, -0.35460489f, -0.56806475f,
   -0.74851075f, -0.88545603f, -0.97094182f, -1.0f,        -0.97094182f,
   -0.88545603f, -0.74851075f, -0.56806475f, -0.35460489f, -0.12053668f,
    0.12053668f,  0.35460489f,  0.56806475f,  0.74851075f,  0.88545603f,
    0.97094182f};
__device__ constexpr float H_SIN[26] = {
    0.0f,         0.23931566f,  0.46472317f,  0.66312266f,  0.82298387f,
    0.93501624f,  0.99270887f,  0.99270887f,  0.93501624f,  0.82298387f,
    0.66312266f,  0.46472317f,  0.23931566f,  0.0f,        -0.23931566f,
   -0.46472317f, -0.66312266f, -0.82298387f, -0.93501624f, -0.99270887f,
   -0.99270887f, -0.93501624f, -0.82298387f, -0.66312266f, -0.46472317f,
   -0.23931566f};

// Exit threshold for bins 1..12: |bin| < 1e-8. Every |G_q| <= 1 so dropped
// bins can never exceed 1e-8 in the reference's final state either; the
// induced log-relative error is ~1e-5, 100x under the 1e-3 gate. Bins 0 (DC)
// and 13 (Nyquist) are EXACTLY real and are finished separately as scalar
// products. bits(1e-8) = 0x322BCC77; compared against (OR of bits)<<1.
#define EXIT_TH2 (0x322BCC77u << 1)

// G[r=(l*64+i)][q] = DFT_q(softmax row r), interleaved (re,im). 852 KB, L2.
__device__ float2 g_G2[NROWS * MOD];

// ---------------------------------------------------------------------------
// Kernel 1 (fused): warp-per-row softmax + 26-point DFT via shfl broadcast.
// ---------------------------------------------------------------------------
__global__ void __launch_bounds__(128)
prep_kernel(const float* __restrict__ key_param,
            float* __restrict__ out_tail, int write_tail) {
    __shared__ float sc[MOD], ss[MOD];
    if (threadIdx.x < MOD) {
        sc[threadIdx.x] = H_COS[threadIdx.x];
        ss[threadIdx.x] = H_SIN[threadIdx.x];
    }
    __syncthreads();

    int warp = threadIdx.x >> 5, lane = threadIdx.x & 31;
    int r = blockIdx.x * 4 + warp;

    float v = (lane < MOD) ? key_param[r * MOD + lane] : -1e30f;
    float m = v;
#pragma unroll
    for (int o = 16; o; o >>= 1) m = fmaxf(m, __shfl_xor_sync(0xffffffffu, m, o));
    float e = (lane < MOD) ? __expf(v - m) : 0.f;
    float s = e;
#pragma unroll
    for (int o = 16; o; o >>= 1) s += __shfl_xor_sync(0xffffffffu, s, o);
    float p = e * (1.f / s);
    if (lane < MOD && write_tail) out_tail[r * MOD + lane] = p;

    int q = (lane < MOD) ? lane : 0;
    float re = 0.f, im = 0.f;
    int t = 0;
#pragma unroll
    for (int k = 0; k < MOD; ++k) {
        float pk = __shfl_sync(0xffffffffu, p, k);
        re = fmaf(pk, sc[t], re);
        im = fmaf(-pk, ss[t], im);
        t += q; if (t >= MOD) t -= MOD;
    }
    if (lane < MOD) g_G2[r * MOD + lane] = make_float2(re, im);
}

// ---------------------------------------------------------------------------
// Kernel 2: chain. Block = one i x 64 b, 256 threads. Four threads per (b,i)
// chain, bins split by quarters with starts {0,4,7,10}. Per-(quarter,p) LUT
// packs 4 byte-offsets. SoA G (conflict-free LDS.32).
// Phase 1: full complex loop until bins 1..12 < 1e-8 (warp vote, ~5-7 steps).
// Phase 2: bins 0 & 13 (exactly real) finished as scalar products, remaining
// steps strided 4-way across the quarter threads, shfl-product reduce.
// Epilogue (common path): dist_c = (1 +/- b13/b0)/26 -> 2 logs + parity pick.
// Rare non-exit path keeps the full shfl-streamed irfft with imm twiddles.
// ---------------------------------------------------------------------------
__global__ void __launch_bounds__(256, 7)
chain_kernel(const int* __restrict__ P, float* __restrict__ out) {
    __shared__ float    sG[2 * NN * 32];   // re at [l*32+s], im at +2048 floats
    __shared__ unsigned sP[16 * 64];       // [l/4][b_local]
    __shared__ unsigned sIdx[4 * 26];      // [q*26+p]: 4 packed byte-offsets
    __shared__ float    sOut[64 * 28];

    int tid = threadIdx.x;
    int i   = blockIdx.x >> 4;
    int b0i = (blockIdx.x & 15) << 6;

    if (tid < 104) {
        int qq = tid / 26, p = tid - qq * 26;
        int js = (qq * 10 + 2) / 3;          // {0,4,7,10}
        unsigned v = 0;
#pragma unroll
        for (int k = 0; k < 4; ++k)
            v |= (unsigned)((((js + k) * p) % MOD) * 4) << (8 * k);
        sIdx[tid] = v;
    }
    for (int m = tid; m < NN * 32; m += 256) {
        int l = m >> 5, s = m & 31;
        if (s < MOD) {
            float2 g = g_G2[((l << 6) | i) * MOD + s];
            sG[m] = g.x; sG[2048 + m] = g.y;
        }
    }
    for (int m = tid; m < 1024; m += 256) {
        int bl = m & 63, l4 = m >> 6;
        int4 pv = *reinterpret_cast<const int4*>(P + ((b0i + bl) << 6) + (l4 << 2));
        sP[(l4 << 6) + bl] = (unsigned)pv.x | ((unsigned)pv.y << 8) |
                             ((unsigned)pv.z << 16) | ((unsigned)pv.w << 24);
    }
    __syncthreads();

    int bl = tid >> 2;
    int q  = tid & 3;
    int hq = q * 26;

    float ar[4], ai[4];
    unsigned w = sP[bl];

    { // l = 0 init
        unsigned idx = sIdx[hq + (w & 255u)];
#pragma unroll
        for (int k = 0; k < 4; ++k) {
            unsigned off = (idx >> (8 * k)) & 255u;
            const float* gp = (const float*)((const char*)sG + off);
            ar[k] = gp[0]; ai[k] = gp[2048];
        }
    }

    auto step = [&](int l, unsigned p) {
        unsigned idx = sIdx[hq + p];
        const char* base = (const char*)sG + (l << 7);
#pragma unroll
        for (int k = 0; k < 4; ++k) {
            unsigned off = (idx >> (8 * k)) & 255u;
            const float* gp = (const float*)(base + off);
            float gr = gp[0];
            float gi = gp[2048];
            float nr = fmaf(ar[k], gr, -ai[k] * gi);
            float ni = fmaf(ar[k], gi,  ai[k] * gr);
            ar[k] = nr; ai[k] = ni;
        }
    };

    // True iff every bin in 1..12 (warp-wide) has |bin| < ~1e-8 (conservative
    // OR-of-bits bound). Masks out DC (q0 k0) and Nyquist (q3 k3).
    auto below12 = [&]() -> bool {
        unsigned nz = __float_as_uint(ar[1]) | __float_as_uint(ai[1]) |
                      __float_as_uint(ar[2]) | __float_as_uint(ai[2]);
        unsigned nz0 = __float_as_uint(ar[0]) | __float_as_uint(ai[0]);
        unsigned nz3 = __float_as_uint(ar[3]) | __float_as_uint(ai[3]);
        nz |= (q != 0) ? nz0 : 0u;
        nz |= (q != 3) ? nz3 : 0u;
        return __all_sync(0xffffffffu, (nz << 1) < EXIT_TH2);
    };

    step(1, (w >> 8) & 255u);
    step(2, (w >> 16) & 255u);
    step(3, (w >> 24) & 255u);

    int lex = 64;    // first unprocessed step on exit
#pragma unroll 1
    for (int lb = 1; lb < 16; ++lb) {
        if (below12()) { lex = lb << 2; break; }
        w = sP[(lb << 6) + bl];
        step(lb * 4 + 0,  w        & 255u);
        step(lb * 4 + 1, (w >> 8)  & 255u);
        if (below12()) { lex = (lb << 2) + 2; break; }
        step(lb * 4 + 2, (w >> 16) & 255u);
        step(lb * 4 + 3, (w >> 24) & 255u);
    }

    int lane  = tid & 31;
    int half  = q & 1;
    unsigned gb = lane & ~3u;
    float* so = sOut + bl * 28 + half * 13;

    if (lex < 64) {
        // Finish real bins 0 & 13: remaining steps strided across quarters.
        float f0 = 1.f, f13 = 1.f;
#pragma unroll 1
        for (int l = lex + q; l < 64; l += 4) {
            unsigned wp = sP[((l >> 2) << 6) + bl];
            unsigned p  = (wp >> ((l & 3) << 3)) & 255u;
            const float* basef = sG + (l << 5);
            f0  *= basef[0];
            f13 *= basef[(p & 1) * 13];
        }
        f0  *= __shfl_xor_sync(0xffffffffu, f0, 1);
        f0  *= __shfl_xor_sync(0xffffffffu, f0, 2);
        f13 *= __shfl_xor_sync(0xffffffffu, f13, 1);
        f13 *= __shfl_xor_sync(0xffffffffu, f13, 2);

        float b0  = __shfl_sync(0xffffffffu, ar[0], gb)     * f0;
        float b13 = __shfl_sync(0xffffffffu, ar[3], gb | 3) * f13;
        float beta = b13 / b0;
        // dist_c = (1 + (-1)^c beta)/26,  c = c0 + 13*half.
        float lpe = __logf(fmaf(1.f + beta, 1.f / 26.f, 1e-12f));
        float lpo = __logf(fmaf(1.f - beta, 1.f / 26.f, 1e-12f));
        if (q < 2) {
#pragma unroll
            for (int c0 = 0; c0 < 13; ++c0)
                so[c0] = ((c0 + half) & 1) ? lpo : lpe;
        }
    } else {
        // Rare path: full irfft via shfl-streamed bins + immediate twiddles.
        float sg = half ? -1.f : 1.f;
        float v[13];

        float b0r = __shfl_sync(0xffffffffu, ar[0], gb);   // DC
#pragma unroll
        for (int c0 = 0; c0 < 13; ++c0) v[c0] = b0r;

#define EPI_J(J, QJ, KJ)                                                      \
        {                                                                     \
            float r_ = __shfl_sync(0xffffffffu, ar[KJ], gb + QJ);             \
            float i_ = __shfl_sync(0xffffffffu, ai[KJ], gb + QJ);             \
            if ((J) & 1) { r_ *= sg; i_ *= sg; }                              \
            _Pragma("unroll")                                                 \
            for (int c0 = 0; c0 < 13; ++c0) {                                 \
                v[c0] = fmaf(r_,  2.f * H_COS[((J) * c0) % MOD], v[c0]);      \
                v[c0] = fmaf(i_, -2.f * H_SIN[((J) * c0) % MOD], v[c0]);      \
            }                                                                 \
        }
        EPI_J(1, 0, 1)  EPI_J(2, 0, 2)  EPI_J(3, 0, 3)
        EPI_J(4, 1, 0)  EPI_J(5, 1, 1)  EPI_J(6, 1, 2)  EPI_J(7, 1, 3)
        EPI_J(8, 2, 1)  EPI_J(9, 2, 2)  EPI_J(10, 2, 3)
        EPI_J(11, 3, 1) EPI_J(12, 3, 2)
#undef EPI_J
        {   // j = 13 (Nyquist): coefficient 1, cos = +/-1, sin = 0.
            float r13 = __shfl_sync(0xffffffffu, ar[3], gb + 3) * sg;
#pragma unroll
            for (int c0 = 0; c0 < 13; ++c0)
                v[c0] += (c0 & 1) ? -r13 : r13;
        }

        if (q < 2) {
            float inv = 1.f / (26.f * b0r);
#pragma unroll
            for (int c0 = 0; c0 < 13; ++c0)
                so[c0] = __logf(fmaf(v[c0], inv, 1e-12f));
        }
    }
    __syncthreads();

    // Coalesced writeout: 8 warps x 8 rows, lanes 0..25 per 104B row.
    int warp = tid >> 5;
    if (lane < MOD) {
#pragma unroll 1
        for (int k = 0; k < 8; ++k) {
            int r = (warp << 3) + k;
            out[(((b0i + r) << 6) | i) * MOD + lane] = sOut[r * 28 + lane];
        }
    }
}

// ---------------------------------------------------------------------------
extern "C" void kernel_launch(void* const* d_in, const int* in_sizes, int n_in,
                              void* d_out, int out_size) {
    const int*   P         = (const int*)d_in[0];    // (1024, 64) int32
    const float* key_param = (const float*)d_in[1];  // (4096, 26) f32
    float*       out       = (float*)d_out;

    const int log_elems = BB * NN * MOD;             // 1,703,936
    const int kp_elems  = NROWS * MOD;               // 106,496
    int write_tail = (out_size >= log_elems + kp_elems) ? 1 : 0;

    prep_kernel<<<NROWS / 4, 128>>>(key_param, out + log_elems, write_tail);
    chain_kernel<<<1024, 256>>>(P, out);
}